// round 12
// baseline (speedup 1.0000x reference)
#include <cuda_runtime.h>
#include <cuda_fp16.h>

#define N_NODES 100000
#define N_EDGES 1600000
#define DIM 128
#define NCHUNKS 98                       // ceil(100000 / 1024)
#define SCAN_FLAG (1 << 30)
#define GEMM_BLOCKS 1563                 // ceil(100000 / 64)
#define HIST_BLOCKS 6250                 // 1.6M / 256
#define BUCKET_BLOCKS 6250
#define AGG_BLOCKS 12500                 // 100000 nodes / 8 per block

// Static device scratch (allocation-free per harness rules).
// g_cnt/g_aggf/g_chist/g_cbuck are zero at module load; each launch restores
// the zero-invariant for the next replay (see resets below). Deterministic.
__device__ __half g_h[N_NODES * DIM];    // h = x@W + b, fp16    (25.6 MB)
__device__ int    g_cnt[N_NODES];        // per-row edge counts (zero on entry)
__device__ int    g_aggf[NCHUNKS];       // scan lookback flags (zero on entry)
__device__ int    g_off[N_NODES + 1];    // CSR row offsets
__device__ int    g_cur[N_NODES];        // bucket cursors
__device__ int2   g_epack[N_EDGES];      // bucketed (col, val-bits) (12.8 MB)
__device__ int    g_chist;               // hist-done counter  (zero on entry)
__device__ int    g_cbuck;               // bucket-done counter(zero on entry)

// ===========================================================================
// LAUNCH 1: blocks [0,1563) GEMM | [1563,7813) hist | [7813,7911) scan.
// Scan blocks spin on g_chist (id-ordered dispatch -> producers always
// dispatched first -> deadlock-free).
// ===========================================================================
__global__ void __launch_bounds__(256)
k_fused1(const float* __restrict__ x, const float* __restrict__ W,
         const float* __restrict__ b, const int* __restrict__ rows) {
    __shared__ __align__(16) __half xs[64 * 128];    // 16 KB (scan reuses)
    __shared__ __align__(16) __half ws[128 * 128];   // 32 KB

    const int tid = threadIdx.x;

    // ---------------- hist blocks ----------------
    if (blockIdx.x >= GEMM_BLOCKS && blockIdx.x < GEMM_BLOCKS + HIST_BLOCKS) {
        const int e = (blockIdx.x - GEMM_BLOCKS) * 256 + tid;
        atomicAdd(&g_cnt[__ldg(&rows[e])], 1);       // 6250*256 == N_EDGES
        __threadfence();
        __syncthreads();
        if (tid == 0) atomicAdd(&g_chist, 1);
        return;
    }

    // ---------------- scan blocks ----------------
    if (blockIdx.x >= GEMM_BLOCKS + HIST_BLOCKS) {
        const int sid = blockIdx.x - GEMM_BLOCKS - HIST_BLOCKS;  // 0..97
        int* ism = (int*)xs;  // [0..7] warp sums, [8..15] warp excl, [16] base

        if (tid == 0)
            while (*(volatile int*)&g_chist != HIST_BLOCKS) __nanosleep(128);
        __syncthreads();

        // 1024-element chunk, 4 per thread via int4 (N_NODES % 4 == 0).
        const int idx4 = sid * 256 + tid;
        int4 c = make_int4(0, 0, 0, 0);
        if (idx4 < N_NODES / 4) c = __ldcg((const int4*)g_cnt + idx4);
        const int s1 = c.x, s2 = s1 + c.y, s3 = s2 + c.z, s4 = s3 + c.w;

        const int lane = tid & 31, wid = tid >> 5;
        int v = s4;                              // warp-inclusive scan of s4
#pragma unroll
        for (int o = 1; o < 32; o <<= 1) {
            const int t = __shfl_up_sync(~0u, v, o);
            if (lane >= o) v += t;
        }
        if (lane == 31) ism[wid] = v;
        __syncthreads();
        if (tid == 0) {
            int acc = 0;
#pragma unroll
            for (int i = 0; i < 8; i++) { const int t = ism[i]; ism[8 + i] = acc; acc += t; }
            __threadfence();
            atomicExch(&g_aggf[sid], acc | SCAN_FLAG);   // publish aggregate
        }
        __syncthreads();
        if (tid < 32) {                          // lookback over predecessors
            int sum = 0;
            for (int p = tid; p < sid; p += 32) {
                int a;
                do { a = *(volatile int*)&g_aggf[p]; } while (!(a & SCAN_FLAG));
                sum += a & ~SCAN_FLAG;
            }
#pragma unroll
            for (int o = 16; o > 0; o >>= 1) sum += __shfl_xor_sync(~0u, sum, o);
            if (tid == 0) ism[16] = sum;
        }
        __syncthreads();
        const int excl = ism[16] + ism[8 + wid] + (v - s4);
        if (idx4 < N_NODES / 4) {
            const int4 off = make_int4(excl, excl + s1, excl + s2, excl + s3);
            ((int4*)g_off)[idx4] = off;
            ((int4*)g_cur)[idx4] = off;
        }
        if (sid == 0 && tid == 0) g_off[N_NODES] = N_EDGES;
        return;
    }

    // ---------------- GEMM blocks ----------------
    if (blockIdx.x == 0 && tid == 0) g_cbuck = 0;  // reset for launch 2

    const int lane = tid & 31;
    const int warp = tid >> 5;
    const int row0 = blockIdx.x * 64;

    const unsigned xs_base = (unsigned)__cvta_generic_to_shared(xs);
    const unsigned ws_base = (unsigned)__cvta_generic_to_shared(ws);

    // Stage x tile: 64 rows x 128 cols fp32 -> fp16, swizzle ^((r&7)<<4).
#pragma unroll
    for (int it = 0; it < 8; it++) {
        const int idx = tid + it * 256;
        const int r = idx >> 5;
        const int q = idx & 31;
        const int grow = row0 + r;
        float4 vv = make_float4(0.f, 0.f, 0.f, 0.f);
        if (grow < N_NODES) vv = *(const float4*)(x + (size_t)grow * DIM + q * 4);
        const __half2 h01 = __floats2half2_rn(vv.x, vv.y);
        const __half2 h23 = __floats2half2_rn(vv.z, vv.w);
        const int byte = (r * 256 + q * 8) ^ ((r & 7) << 4);
        *(uint2*)((char*)xs + byte) =
            make_uint2(*(const unsigned*)&h01, *(const unsigned*)&h23);
    }
    // Stage full W 128x128, swizzle ^((k&7)<<4).
#pragma unroll
    for (int it = 0; it < 16; it++) {
        const int idx = tid + it * 256;
        const int k = idx >> 5;
        const int q = idx & 31;
        const float4 vv = *(const float4*)(W + (size_t)k * DIM + q * 4);
        const __half2 h01 = __floats2half2_rn(vv.x, vv.y);
        const __half2 h23 = __floats2half2_rn(vv.z, vv.w);
        const int byte = (k * 256 + q * 8) ^ ((k & 7) << 4);
        *(uint2*)((char*)ws + byte) =
            make_uint2(*(const unsigned*)&h01, *(const unsigned*)&h23);
    }
    __syncthreads();

    const int wr    = warp & 3;
    const int nbase = (warp >> 2) * 64;

    float acc[8][4];
#pragma unroll
    for (int i = 0; i < 8; i++)
#pragma unroll
        for (int j = 0; j < 4; j++) acc[i][j] = 0.f;

    const int ar    = wr * 16 + (lane & 15);
    const int akoff = (lane >> 4) << 3;
    const int bm    = lane >> 3;
    const int bkrow = ((bm & 1) << 3) + (lane & 7);
    const int bnoff = (bm >> 1) << 3;

#pragma unroll
    for (int ks = 0; ks < 8; ks++) {
        const int k0 = ks * 16;
        unsigned a0, a1, a2, a3;
        {
            const int kk = k0 + akoff;
            const unsigned addr =
                xs_base + ((ar * 256 + kk * 2) ^ ((ar & 7) << 4));
            asm volatile(
                "ldmatrix.sync.aligned.m8n8.x4.shared.b16 {%0,%1,%2,%3}, [%4];"
                : "=r"(a0), "=r"(a1), "=r"(a2), "=r"(a3) : "r"(addr));
        }
#pragma unroll
        for (int p = 0; p < 4; p++) {
            unsigned b0, b1, b2, b3;
            const int kk = k0 + bkrow;
            const int nn = nbase + p * 16 + bnoff;
            const unsigned addr =
                ws_base + ((kk * 256 + nn * 2) ^ ((kk & 7) << 4));
            asm volatile(
                "ldmatrix.sync.aligned.m8n8.x4.trans.shared.b16 {%0,%1,%2,%3}, [%4];"
                : "=r"(b0), "=r"(b1), "=r"(b2), "=r"(b3) : "r"(addr));
            asm volatile(
                "mma.sync.aligned.m16n8k16.row.col.f32.f16.f16.f32 "
                "{%0,%1,%2,%3}, {%4,%5,%6,%7}, {%8,%9}, {%0,%1,%2,%3};"
                : "+f"(acc[2 * p][0]), "+f"(acc[2 * p][1]),
                  "+f"(acc[2 * p][2]), "+f"(acc[2 * p][3])
                : "r"(a0), "r"(a1), "r"(a2), "r"(a3), "r"(b0), "r"(b1));
            asm volatile(
                "mma.sync.aligned.m16n8k16.row.col.f32.f16.f16.f32 "
                "{%0,%1,%2,%3}, {%4,%5,%6,%7}, {%8,%9}, {%0,%1,%2,%3};"
                : "+f"(acc[2 * p + 1][0]), "+f"(acc[2 * p + 1][1]),
                  "+f"(acc[2 * p + 1][2]), "+f"(acc[2 * p + 1][3])
                : "r"(a0), "r"(a1), "r"(a2), "r"(a3), "r"(b2), "r"(b3));
        }
    }

    const int r0 = row0 + wr * 16 + (lane >> 2);
    const int r1 = r0 + 8;
    const int cbase = nbase + ((lane & 3) << 1);
#pragma unroll
    for (int i = 0; i < 8; i++) {
        const int n = cbase + i * 8;
        const float2 bb = *(const float2*)(b + n);
        const __half2 lo = __floats2half2_rn(acc[i][0] + bb.x, acc[i][1] + bb.y);
        const __half2 hi = __floats2half2_rn(acc[i][2] + bb.x, acc[i][3] + bb.y);
        if (r0 < N_NODES) *(__half2*)(g_h + (size_t)r0 * DIM + n) = lo;
        if (r1 < N_NODES) *(__half2*)(g_h + (size_t)r1 * DIM + n) = hi;
    }
}

// ===========================================================================
// LAUNCH 2: blocks [0,6250) bucket | [6250,18750) agg (8 nodes/block).
// Agg blocks spin on g_cbuck; bucket ids precede agg ids -> deadlock-free.
// ===========================================================================
__global__ void __launch_bounds__(256)
k_fused2(const int* __restrict__ rows, const int* __restrict__ cols,
         const float* __restrict__ vals, float* __restrict__ out) {
    const int tid = threadIdx.x;

    if (blockIdx.x < BUCKET_BLOCKS) {
        // ---------------- bucket ----------------
        if (blockIdx.x == 0 && tid == 0) g_chist = 0;   // reset for next replay
        const int e = blockIdx.x * 256 + tid;
        if (e < N_NODES) g_cnt[e] = 0;                  // restore zero-invariant
        if (e < NCHUNKS) g_aggf[e] = 0;
        const int p = atomicAdd(&g_cur[rows[e]], 1);    // 6250*256 == N_EDGES
        g_epack[p] = make_int2(cols[e], __float_as_int(vals[e]));
        __threadfence();
        __syncthreads();
        if (tid == 0) atomicAdd(&g_cbuck, 1);
        return;
    }

    // ---------------- aggregate ----------------
    // One warp per node. Half-warp split: lanes 0-15 handle edge e, lanes
    // 16-31 handle edge e+1; each lane covers 8 cols (uint4 = 8 halfs).
    if (tid == 0)
        while (*(volatile int*)&g_cbuck != BUCKET_BLOCKS) __nanosleep(128);
    __syncthreads();
    __threadfence();

    const int node = (blockIdx.x - BUCKET_BLOCKS) * 8 + (tid >> 5);
    const int lane = tid & 31;
    const int half = lane >> 4;
    const int hl   = lane & 15;

    const int start = g_off[node];
    const int end   = g_off[node + 1];

    float acc[8];
#pragma unroll
    for (int j = 0; j < 8; j++) acc[j] = 0.f;

    int e = start;
    for (; e + 4 <= end; e += 4) {          // 2 steps = 4 edges, fully valid
        const int2 pa = g_epack[e + half];
        const int2 pb = g_epack[e + 2 + half];
        const uint4 ua = *(const uint4*)(g_h + (size_t)pa.x * DIM + hl * 8);
        const uint4 ub = *(const uint4*)(g_h + (size_t)pb.x * DIM + hl * 8);
        const float va = __int_as_float(pa.y);
        const float vb = __int_as_float(pb.y);
        float2 f;
        f = __half22float2(*(const __half2*)&ua.x); acc[0] += va * f.x; acc[1] += va * f.y;
        f = __half22float2(*(const __half2*)&ua.y); acc[2] += va * f.x; acc[3] += va * f.y;
        f = __half22float2(*(const __half2*)&ua.z); acc[4] += va * f.x; acc[5] += va * f.y;
        f = __half22float2(*(const __half2*)&ua.w); acc[6] += va * f.x; acc[7] += va * f.y;
        f = __half22float2(*(const __half2*)&ub.x); acc[0] += vb * f.x; acc[1] += vb * f.y;
        f = __half22float2(*(const __half2*)&ub.y); acc[2] += vb * f.x; acc[3] += vb * f.y;
        f = __half22float2(*(const __half2*)&ub.z); acc[4] += vb * f.x; acc[5] += vb * f.y;
        f = __half22float2(*(const __half2*)&ub.w); acc[6] += vb * f.x; acc[7] += vb * f.y;
    }
    for (; e < end; e += 2) {               // tail: per-half validity via v=0
        const int ee = e + half;
        int2 p = make_int2(0, 0);
        if (ee < end) p = g_epack[ee];
        const uint4 u = *(const uint4*)(g_h + (size_t)p.x * DIM + hl * 8);
        const float v = __int_as_float(p.y);
        float2 f;
        f = __half22float2(*(const __half2*)&u.x); acc[0] += v * f.x; acc[1] += v * f.y;
        f = __half22float2(*(const __half2*)&u.y); acc[2] += v * f.x; acc[3] += v * f.y;
        f = __half22float2(*(const __half2*)&u.z); acc[4] += v * f.x; acc[5] += v * f.y;
        f = __half22float2(*(const __half2*)&u.w); acc[6] += v * f.x; acc[7] += v * f.y;
    }

    // Cross-half reduction: even-edge stream + odd-edge stream.
#pragma unroll
    for (int j = 0; j < 8; j++)
        acc[j] += __shfl_down_sync(0xffffffffu, acc[j], 16);

    if (half == 0) {
        float* dst = out + (size_t)node * DIM + hl * 8;
        *(float4*)dst       = make_float4(acc[0], acc[1], acc[2], acc[3]);
        *(float4*)(dst + 4) = make_float4(acc[4], acc[5], acc[6], acc[7]);
    }
}

// ---------------------------------------------------------------------------
// Launcher: 2 plain kernel launches (graph-capture safe).
// ---------------------------------------------------------------------------
extern "C" void kernel_launch(void* const* d_in, const int* in_sizes, int n_in,
                              void* d_out, int out_size) {
    const float* x    = (const float*)d_in[0];
    const float* W    = (const float*)d_in[1];
    const float* b    = (const float*)d_in[2];
    const float* vals = (const float*)d_in[3];
    const int*   rows = (const int*)d_in[4];
    const int*   cols = (const int*)d_in[5];
    float* out = (float*)d_out;

    (void)in_sizes; (void)n_in; (void)out_size;

    k_fused1<<<GEMM_BLOCKS + HIST_BLOCKS + NCHUNKS, 256>>>(x, W, b, rows);
    k_fused2<<<BUCKET_BLOCKS + AGG_BLOCKS, 256>>>(rows, cols, vals, out);
}

// round 13
// speedup vs baseline: 1.2365x; 1.2365x over previous
#include <cuda_runtime.h>
#include <cuda_fp16.h>

#define N_NODES 100000
#define N_EDGES 1600000
#define DIM 128
#define SCAN_CHUNK 1024
#define NCHUNKS ((N_NODES + SCAN_CHUNK - 1) / SCAN_CHUNK)  // 98
#define SCAN_FLAG (1 << 30)
#define GEMM_BLOCKS ((N_NODES + 63) / 64)          // 1563
#define HIST_BLOCKS ((N_EDGES + 255) / 256)        // 6250
#define AGG_BLOCKS ((N_NODES + 7) / 8)             // 12500

// Static device scratch (allocation-free per harness rules).
// g_cnt / g_aggf zero at module load; k_bucket re-zeros them each launch.
__device__ __half g_h[N_NODES * DIM];    // h = x@W + b, fp16    (25.6 MB)
__device__ int    g_cnt[N_NODES];        // per-row edge counts (zero on entry)
__device__ int    g_aggf[NCHUNKS];       // lookback flags      (zero on entry)
__device__ int    g_off[N_NODES + 1];    // CSR row offsets
__device__ int    g_cur[N_NODES];        // bucket cursors
__device__ int2   g_epack[N_EDGES];      // bucketed (col, val-bits) (12.8 MB)

// ---------------------------------------------------------------------------
// LAUNCH 1: blocks [0, GEMM_BLOCKS) = HMMA GEMM tile (64 rows x 128 cols);
// blocks [GEMM_BLOCKS, +HIST_BLOCKS) = edge histogram. Independent phases,
// hist hides behind the GEMM wave. (Proven round-9 structure.)
// ---------------------------------------------------------------------------
__global__ void __launch_bounds__(256)
k_gemm_hist(const float* __restrict__ x, const float* __restrict__ W,
            const float* __restrict__ b, const int* __restrict__ rows) {
    if (blockIdx.x >= GEMM_BLOCKS) {
        const int e = (blockIdx.x - GEMM_BLOCKS) * 256 + threadIdx.x;
        if (e < N_EDGES) atomicAdd(&g_cnt[__ldg(&rows[e])], 1);
        return;
    }

    __shared__ __align__(16) __half xs[64 * 128];    // 16 KB, swizzled
    __shared__ __align__(16) __half ws[128 * 128];   // 32 KB, swizzled

    const int tid  = threadIdx.x;
    const int lane = tid & 31;
    const int warp = tid >> 5;
    const int row0 = blockIdx.x * 64;

    const unsigned xs_base = (unsigned)__cvta_generic_to_shared(xs);
    const unsigned ws_base = (unsigned)__cvta_generic_to_shared(ws);

    // Stage x tile: 64 rows x 128 cols fp32 -> fp16, swizzle ^((r&7)<<4).
#pragma unroll
    for (int it = 0; it < 8; it++) {
        const int idx = tid + it * 256;
        const int r = idx >> 5;
        const int q = idx & 31;
        const int grow = row0 + r;
        float4 v = make_float4(0.f, 0.f, 0.f, 0.f);
        if (grow < N_NODES) v = *(const float4*)(x + (size_t)grow * DIM + q * 4);
        const __half2 h01 = __floats2half2_rn(v.x, v.y);
        const __half2 h23 = __floats2half2_rn(v.z, v.w);
        const int byte = (r * 256 + q * 8) ^ ((r & 7) << 4);
        *(uint2*)((char*)xs + byte) =
            make_uint2(*(const unsigned*)&h01, *(const unsigned*)&h23);
    }
    // Stage W: full 128 k x 128 n, swizzle ^((k&7)<<4). (L2-hot across blocks.)
#pragma unroll
    for (int it = 0; it < 16; it++) {
        const int idx = tid + it * 256;
        const int k = idx >> 5;
        const int q = idx & 31;
        const float4 v = *(const float4*)(W + (size_t)k * DIM + q * 4);
        const __half2 h01 = __floats2half2_rn(v.x, v.y);
        const __half2 h23 = __floats2half2_rn(v.z, v.w);
        const int byte = (k * 256 + q * 8) ^ ((k & 7) << 4);
        *(uint2*)((char*)ws + byte) =
            make_uint2(*(const unsigned*)&h01, *(const unsigned*)&h23);
    }
    __syncthreads();

    // Warps 0-3 -> row slabs, cols 0..63; warps 4-7 -> same slabs, cols 64..127.
    const int wr    = warp & 3;
    const int nbase = (warp >> 2) * 64;

    float acc[8][4];
#pragma unroll
    for (int i = 0; i < 8; i++)
#pragma unroll
        for (int j = 0; j < 4; j++) acc[i][j] = 0.f;

    const int ar    = wr * 16 + (lane & 15);
    const int akoff = (lane >> 4) << 3;
    const int bm    = lane >> 3;
    const int bkrow = ((bm & 1) << 3) + (lane & 7);
    const int bnoff = (bm >> 1) << 3;

#pragma unroll
    for (int ks = 0; ks < 8; ks++) {
        const int k0 = ks * 16;
        unsigned a0, a1, a2, a3;
        {
            const int kk = k0 + akoff;
            const unsigned addr =
                xs_base + ((ar * 256 + kk * 2) ^ ((ar & 7) << 4));
            asm volatile(
                "ldmatrix.sync.aligned.m8n8.x4.shared.b16 {%0,%1,%2,%3}, [%4];"
                : "=r"(a0), "=r"(a1), "=r"(a2), "=r"(a3) : "r"(addr));
        }
#pragma unroll
        for (int p = 0; p < 4; p++) {
            unsigned b0, b1, b2, b3;
            const int kk = k0 + bkrow;
            const int nn = nbase + p * 16 + bnoff;
            const unsigned addr =
                ws_base + ((kk * 256 + nn * 2) ^ ((kk & 7) << 4));
            asm volatile(
                "ldmatrix.sync.aligned.m8n8.x4.trans.shared.b16 {%0,%1,%2,%3}, [%4];"
                : "=r"(b0), "=r"(b1), "=r"(b2), "=r"(b3) : "r"(addr));
            asm volatile(
                "mma.sync.aligned.m16n8k16.row.col.f32.f16.f16.f32 "
                "{%0,%1,%2,%3}, {%4,%5,%6,%7}, {%8,%9}, {%0,%1,%2,%3};"
                : "+f"(acc[2 * p][0]), "+f"(acc[2 * p][1]),
                  "+f"(acc[2 * p][2]), "+f"(acc[2 * p][3])
                : "r"(a0), "r"(a1), "r"(a2), "r"(a3), "r"(b0), "r"(b1));
            asm volatile(
                "mma.sync.aligned.m16n8k16.row.col.f32.f16.f16.f32 "
                "{%0,%1,%2,%3}, {%4,%5,%6,%7}, {%8,%9}, {%0,%1,%2,%3};"
                : "+f"(acc[2 * p + 1][0]), "+f"(acc[2 * p + 1][1]),
                  "+f"(acc[2 * p + 1][2]), "+f"(acc[2 * p + 1][3])
                : "r"(a0), "r"(a1), "r"(a2), "r"(a3), "r"(b2), "r"(b3));
        }
    }

    const int r0 = row0 + wr * 16 + (lane >> 2);
    const int r1 = r0 + 8;
    const int cbase = nbase + ((lane & 3) << 1);
#pragma unroll
    for (int i = 0; i < 8; i++) {
        const int n = cbase + i * 8;
        const float2 bb = *(const float2*)(b + n);
        const __half2 lo = __floats2half2_rn(acc[i][0] + bb.x, acc[i][1] + bb.y);
        const __half2 hi = __floats2half2_rn(acc[i][2] + bb.x, acc[i][3] + bb.y);
        if (r0 < N_NODES) *(__half2*)(g_h + (size_t)r0 * DIM + n) = lo;
        if (r1 < N_NODES) *(__half2*)(g_h + (size_t)r1 * DIM + n) = hi;
    }
}

// ---------------------------------------------------------------------------
// LAUNCH 2: decoupled-lookback exclusive scan; 98 blocks < 148 SMs.
// ---------------------------------------------------------------------------
__global__ void __launch_bounds__(1024) k_scan() {
    __shared__ int s[SCAN_CHUNK];
    __shared__ int base_sh;
    const int blk = blockIdx.x;
    const int i = blk * SCAN_CHUNK + threadIdx.x;
    const int v = (i < N_NODES) ? g_cnt[i] : 0;
    s[threadIdx.x] = v;
    __syncthreads();
#pragma unroll
    for (int st = 1; st < SCAN_CHUNK; st <<= 1) {
        const int t = (threadIdx.x >= st) ? s[threadIdx.x - st] : 0;
        __syncthreads();
        s[threadIdx.x] += t;
        __syncthreads();
    }
    if (threadIdx.x == SCAN_CHUNK - 1) {
        __threadfence();
        atomicExch(&g_aggf[blk], s[SCAN_CHUNK - 1] | SCAN_FLAG);
    }
    if (threadIdx.x < 32) {
        int sum = 0;
        for (int p = (int)threadIdx.x; p < blk; p += 32) {
            int a;
            do { a = atomicAdd(&g_aggf[p], 0); } while (!(a & SCAN_FLAG));
            sum += a & ~SCAN_FLAG;
        }
#pragma unroll
        for (int o = 16; o > 0; o >>= 1) sum += __shfl_xor_sync(~0u, sum, o);
        if (threadIdx.x == 0) base_sh = sum;
    }
    __syncthreads();
    if (i < N_NODES) {
        const int excl = base_sh + s[threadIdx.x] - v;
        g_off[i] = excl;
        g_cur[i] = excl;
    }
    if (i == 0) g_off[N_NODES] = N_EDGES;
}

// ---------------------------------------------------------------------------
// LAUNCH 3: bucket edges into CSR order; restore g_cnt/g_aggf zero-invariant.
// ---------------------------------------------------------------------------
__global__ void __launch_bounds__(256)
k_bucket(const int* __restrict__ rows, const int* __restrict__ cols,
         const float* __restrict__ vals) {
    const int e = blockIdx.x * 256 + threadIdx.x;
    if (e < N_NODES) g_cnt[e] = 0;
    if (e < NCHUNKS) g_aggf[e] = 0;
    if (e >= N_EDGES) return;
    const int p = atomicAdd(&g_cur[rows[e]], 1);
    g_epack[p] = make_int2(cols[e], __float_as_int(vals[e]));
}

// ---------------------------------------------------------------------------
// LAUNCH 4: aggregate. One warp per node, half-warp split:
// lanes 0-15 handle edge e, lanes 16-31 edge e+1; each lane 8 cols via one
// uint4 (LDG.128). Cross-half shfl reduction at the end. No atomics.
// ---------------------------------------------------------------------------
__global__ void __launch_bounds__(256)
k_agg(float* __restrict__ out) {
    const int node = (blockIdx.x * 256 + threadIdx.x) >> 5;
    if (node >= N_NODES) return;
    const int lane = threadIdx.x & 31;
    const int half = lane >> 4;
    const int hl   = lane & 15;

    const int start = g_off[node];
    const int end   = g_off[node + 1];

    float acc[8];
#pragma unroll
    for (int j = 0; j < 8; j++) acc[j] = 0.f;

    int e = start;
    for (; e + 4 <= end; e += 4) {          // 2 edges per half per step
        const int2 pa = g_epack[e + half];
        const int2 pb = g_epack[e + 2 + half];
        const uint4 ua = *(const uint4*)(g_h + (size_t)pa.x * DIM + hl * 8);
        const uint4 ub = *(const uint4*)(g_h + (size_t)pb.x * DIM + hl * 8);
        const float va = __int_as_float(pa.y);
        const float vb = __int_as_float(pb.y);
        float2 f;
        f = __half22float2(*(const __half2*)&ua.x); acc[0] += va * f.x; acc[1] += va * f.y;
        f = __half22float2(*(const __half2*)&ua.y); acc[2] += va * f.x; acc[3] += va * f.y;
        f = __half22float2(*(const __half2*)&ua.z); acc[4] += va * f.x; acc[5] += va * f.y;
        f = __half22float2(*(const __half2*)&ua.w); acc[6] += va * f.x; acc[7] += va * f.y;
        f = __half22float2(*(const __half2*)&ub.x); acc[0] += vb * f.x; acc[1] += vb * f.y;
        f = __half22float2(*(const __half2*)&ub.y); acc[2] += vb * f.x; acc[3] += vb * f.y;
        f = __half22float2(*(const __half2*)&ub.z); acc[4] += vb * f.x; acc[5] += vb * f.y;
        f = __half22float2(*(const __half2*)&ub.w); acc[6] += vb * f.x; acc[7] += vb * f.y;
    }
    for (; e < end; e += 2) {               // tail: per-half validity via v=0
        const int ee = e + half;
        int2 p = make_int2(0, 0);
        if (ee < end) p = g_epack[ee];
        const uint4 u = *(const uint4*)(g_h + (size_t)p.x * DIM + hl * 8);
        const float v = __int_as_float(p.y);
        float2 f;
        f = __half22float2(*(const __half2*)&u.x); acc[0] += v * f.x; acc[1] += v * f.y;
        f = __half22float2(*(const __half2*)&u.y); acc[2] += v * f.x; acc[3] += v * f.y;
        f = __half22float2(*(const __half2*)&u.z); acc[4] += v * f.x; acc[5] += v * f.y;
        f = __half22float2(*(const __half2*)&u.w); acc[6] += v * f.x; acc[7] += v * f.y;
    }

    // Combine even-edge (half 0) and odd-edge (half 1) partial sums.
#pragma unroll
    for (int j = 0; j < 8; j++)
        acc[j] += __shfl_down_sync(0xffffffffu, acc[j], 16);

    if (half == 0) {
        float* dst = out + (size_t)node * DIM + hl * 8;
        *(float4*)dst       = make_float4(acc[0], acc[1], acc[2], acc[3]);
        *(float4*)(dst + 4) = make_float4(acc[4], acc[5], acc[6], acc[7]);
    }
}

// ---------------------------------------------------------------------------
// Launcher: 4 plain kernel launches (graph-capture safe).
// ---------------------------------------------------------------------------
extern "C" void kernel_launch(void* const* d_in, const int* in_sizes, int n_in,
                              void* d_out, int out_size) {
    const float* x    = (const float*)d_in[0];
    const float* W    = (const float*)d_in[1];
    const float* b    = (const float*)d_in[2];
    const float* vals = (const float*)d_in[3];
    const int*   rows = (const int*)d_in[4];
    const int*   cols = (const int*)d_in[5];
    float* out = (float*)d_out;

    (void)in_sizes; (void)n_in; (void)out_size;

    k_gemm_hist<<<GEMM_BLOCKS + HIST_BLOCKS, 256>>>(x, W, b, rows);
    k_scan<<<NCHUNKS, SCAN_CHUNK>>>();
    k_bucket<<<(N_EDGES + 255) / 256, 256>>>(rows, cols, vals);
    k_agg<<<AGG_BLOCKS, 256>>>(out);
}

// round 14
// speedup vs baseline: 1.2598x; 1.0188x over previous
#include <cuda_runtime.h>
#include <cuda_fp16.h>

#define N_NODES 100000
#define N_EDGES 1600000
#define DIM 128
#define NCHUNKS 98                       // ceil(100000 / 1024)
#define SCAN_FLAG (1 << 30)
#define GEMM_BLOCKS 1563                 // ceil(100000 / 64)
#define HIST_BLOCKS 6250                 // 1.6M / 256

// Static device scratch (allocation-free per harness rules).
// g_cnt / g_aggf zero at module load; k_scan re-zeros g_cnt, k_bucket g_aggf.
__device__ __half g_h[N_NODES * DIM];    // h = x@W + b, fp16    (25.6 MB)
__device__ int    g_cnt[N_NODES];        // per-row edge counts (zero on entry)
__device__ int    g_aggf[NCHUNKS];       // lookback flags      (zero on entry)
__device__ int    g_off[N_NODES + 1];    // CSR row offsets
__device__ int    g_cur[N_NODES];        // bucket cursors
__device__ int2   g_epack[N_EDGES];      // bucketed (col, val-bits) (12.8 MB)

// ---------------------------------------------------------------------------
// LAUNCH 1: blocks [0, GEMM_BLOCKS) = HMMA GEMM tile (64 rows x 128 cols);
// blocks [GEMM_BLOCKS, +HIST_BLOCKS) = edge histogram. Independent phases.
// ---------------------------------------------------------------------------
__global__ void __launch_bounds__(256)
k_gemm_hist(const float* __restrict__ x, const float* __restrict__ W,
            const float* __restrict__ b, const int* __restrict__ rows) {
    if (blockIdx.x >= GEMM_BLOCKS) {
        const int e = (blockIdx.x - GEMM_BLOCKS) * 256 + threadIdx.x;
        if (e < N_EDGES) atomicAdd(&g_cnt[__ldg(&rows[e])], 1);
        return;
    }

    __shared__ __align__(16) __half xs[64 * 128];    // 16 KB, swizzled
    __shared__ __align__(16) __half ws[128 * 128];   // 32 KB, swizzled

    const int tid  = threadIdx.x;
    const int lane = tid & 31;
    const int warp = tid >> 5;
    const int row0 = blockIdx.x * 64;

    const unsigned xs_base = (unsigned)__cvta_generic_to_shared(xs);
    const unsigned ws_base = (unsigned)__cvta_generic_to_shared(ws);

    // Stage x tile: 64 rows x 128 cols fp32 -> fp16, swizzle ^((r&7)<<4).
#pragma unroll
    for (int it = 0; it < 8; it++) {
        const int idx = tid + it * 256;
        const int r = idx >> 5;
        const int q = idx & 31;
        const int grow = row0 + r;
        float4 v = make_float4(0.f, 0.f, 0.f, 0.f);
        if (grow < N_NODES) v = *(const float4*)(x + (size_t)grow * DIM + q * 4);
        const __half2 h01 = __floats2half2_rn(v.x, v.y);
        const __half2 h23 = __floats2half2_rn(v.z, v.w);
        const int byte = (r * 256 + q * 8) ^ ((r & 7) << 4);
        *(uint2*)((char*)xs + byte) =
            make_uint2(*(const unsigned*)&h01, *(const unsigned*)&h23);
    }
    // Stage W: full 128 k x 128 n, swizzle ^((k&7)<<4).
#pragma unroll
    for (int it = 0; it < 16; it++) {
        const int idx = tid + it * 256;
        const int k = idx >> 5;
        const int q = idx & 31;
        const float4 v = *(const float4*)(W + (size_t)k * DIM + q * 4);
        const __half2 h01 = __floats2half2_rn(v.x, v.y);
        const __half2 h23 = __floats2half2_rn(v.z, v.w);
        const int byte = (k * 256 + q * 8) ^ ((k & 7) << 4);
        *(uint2*)((char*)ws + byte) =
            make_uint2(*(const unsigned*)&h01, *(const unsigned*)&h23);
    }
    __syncthreads();

    const int wr    = warp & 3;
    const int nbase = (warp >> 2) * 64;

    float acc[8][4];
#pragma unroll
    for (int i = 0; i < 8; i++)
#pragma unroll
        for (int j = 0; j < 4; j++) acc[i][j] = 0.f;

    const int ar    = wr * 16 + (lane & 15);
    const int akoff = (lane >> 4) << 3;
    const int bm    = lane >> 3;
    const int bkrow = ((bm & 1) << 3) + (lane & 7);
    const int bnoff = (bm >> 1) << 3;

#pragma unroll
    for (int ks = 0; ks < 8; ks++) {
        const int k0 = ks * 16;
        unsigned a0, a1, a2, a3;
        {
            const int kk = k0 + akoff;
            const unsigned addr =
                xs_base + ((ar * 256 + kk * 2) ^ ((ar & 7) << 4));
            asm volatile(
                "ldmatrix.sync.aligned.m8n8.x4.shared.b16 {%0,%1,%2,%3}, [%4];"
                : "=r"(a0), "=r"(a1), "=r"(a2), "=r"(a3) : "r"(addr));
        }
#pragma unroll
        for (int p = 0; p < 4; p++) {
            unsigned b0, b1, b2, b3;
            const int kk = k0 + bkrow;
            const int nn = nbase + p * 16 + bnoff;
            const unsigned addr =
                ws_base + ((kk * 256 + nn * 2) ^ ((kk & 7) << 4));
            asm volatile(
                "ldmatrix.sync.aligned.m8n8.x4.trans.shared.b16 {%0,%1,%2,%3}, [%4];"
                : "=r"(b0), "=r"(b1), "=r"(b2), "=r"(b3) : "r"(addr));
            asm volatile(
                "mma.sync.aligned.m16n8k16.row.col.f32.f16.f16.f32 "
                "{%0,%1,%2,%3}, {%4,%5,%6,%7}, {%8,%9}, {%0,%1,%2,%3};"
                : "+f"(acc[2 * p][0]), "+f"(acc[2 * p][1]),
                  "+f"(acc[2 * p][2]), "+f"(acc[2 * p][3])
                : "r"(a0), "r"(a1), "r"(a2), "r"(a3), "r"(b0), "r"(b1));
            asm volatile(
                "mma.sync.aligned.m16n8k16.row.col.f32.f16.f16.f32 "
                "{%0,%1,%2,%3}, {%4,%5,%6,%7}, {%8,%9}, {%0,%1,%2,%3};"
                : "+f"(acc[2 * p + 1][0]), "+f"(acc[2 * p + 1][1]),
                  "+f"(acc[2 * p + 1][2]), "+f"(acc[2 * p + 1][3])
                : "r"(a0), "r"(a1), "r"(a2), "r"(a3), "r"(b2), "r"(b3));
        }
    }

    const int r0 = row0 + wr * 16 + (lane >> 2);
    const int r1 = r0 + 8;
    const int cbase = nbase + ((lane & 3) << 1);
#pragma unroll
    for (int i = 0; i < 8; i++) {
        const int n = cbase + i * 8;
        const float2 bb = *(const float2*)(b + n);
        const __half2 lo = __floats2half2_rn(acc[i][0] + bb.x, acc[i][1] + bb.y);
        const __half2 hi = __floats2half2_rn(acc[i][2] + bb.x, acc[i][3] + bb.y);
        if (r0 < N_NODES) *(__half2*)(g_h + (size_t)r0 * DIM + n) = lo;
        if (r1 < N_NODES) *(__half2*)(g_h + (size_t)r1 * DIM + n) = hi;
    }
}

// ---------------------------------------------------------------------------
// LAUNCH 2: shfl-based decoupled-lookback exclusive scan (256 thr, int4 per
// thread = 1024 elems/block, 98 blocks < 148 SMs). Also re-zeros the g_cnt
// chunk it consumed (restores the zero-invariant for the next replay).
// ---------------------------------------------------------------------------
__global__ void __launch_bounds__(256) k_scan() {
    __shared__ int ism[17];  // [0..7] warp sums, [8..15] warp excl, [16] base
    const int tid = threadIdx.x;
    const int sid = blockIdx.x;
    const int idx4 = sid * 256 + tid;

    int4 c = make_int4(0, 0, 0, 0);
    if (idx4 < N_NODES / 4) c = ((const int4*)g_cnt)[idx4];
    const int s1 = c.x, s2 = s1 + c.y, s3 = s2 + c.z, s4 = s3 + c.w;

    const int lane = tid & 31, wid = tid >> 5;
    int v = s4;                              // warp-inclusive scan of s4
#pragma unroll
    for (int o = 1; o < 32; o <<= 1) {
        const int t = __shfl_up_sync(~0u, v, o);
        if (lane >= o) v += t;
    }
    if (lane == 31) ism[wid] = v;
    __syncthreads();
    if (tid == 0) {
        int acc = 0;
#pragma unroll
        for (int i = 0; i < 8; i++) { const int t = ism[i]; ism[8 + i] = acc; acc += t; }
        __threadfence();
        atomicExch(&g_aggf[sid], acc | SCAN_FLAG);   // publish aggregate
    }
    __syncthreads();
    if (tid < 32) {                          // lookback over predecessors
        int sum = 0;
        for (int p = tid; p < sid; p += 32) {
            int a;
            do { a = *(volatile int*)&g_aggf[p]; } while (!(a & SCAN_FLAG));
            sum += a & ~SCAN_FLAG;
        }
#pragma unroll
        for (int o = 16; o > 0; o >>= 1) sum += __shfl_xor_sync(~0u, sum, o);
        if (tid == 0) ism[16] = sum;
    }
    __syncthreads();
    const int excl = ism[16] + ism[8 + wid] + (v - s4);
    if (idx4 < N_NODES / 4) {
        const int4 off = make_int4(excl, excl + s1, excl + s2, excl + s3);
        ((int4*)g_off)[idx4] = off;
        ((int4*)g_cur)[idx4] = off;
        ((int4*)g_cnt)[idx4] = make_int4(0, 0, 0, 0);  // restore invariant
    }
    if (sid == 0 && tid == 0) g_off[N_NODES] = N_EDGES;
}

// ---------------------------------------------------------------------------
// LAUNCH 3: bucket edges into CSR order; restore g_aggf zero-invariant.
// ---------------------------------------------------------------------------
__global__ void __launch_bounds__(256)
k_bucket(const int* __restrict__ rows, const int* __restrict__ cols,
         const float* __restrict__ vals) {
    const int e = blockIdx.x * 256 + threadIdx.x;
    if (e < NCHUNKS) g_aggf[e] = 0;
    if (e >= N_EDGES) return;
    const int p = atomicAdd(&g_cur[rows[e]], 1);
    g_epack[p] = make_int2(cols[e], __float_as_int(vals[e]));
}

// ---------------------------------------------------------------------------
// LAUNCH 4: aggregate. One warp per node (round-9 layout: lane = 4 cols via
// uint2), 8-edge batch with TWO independent accumulator sets for 8 gathers
// in flight + 2 independent FMA chains. No atomics.
// ---------------------------------------------------------------------------
__global__ void __launch_bounds__(256)
k_agg(float* __restrict__ out) {
    const int node = (blockIdx.x * 256 + threadIdx.x) >> 5;
    if (node >= N_NODES) return;
    const int lane = threadIdx.x & 31;
    const int c4 = lane * 4;

    const int start = g_off[node];
    const int end   = g_off[node + 1];

    float4 accA = make_float4(0.f, 0.f, 0.f, 0.f);
    float4 accB = make_float4(0.f, 0.f, 0.f, 0.f);

    int e = start;
    for (; e + 8 <= end; e += 8) {
        int2 p[8];
#pragma unroll
        for (int q = 0; q < 8; q++) p[q] = g_epack[e + q];
        uint2 u[8];
#pragma unroll
        for (int q = 0; q < 8; q++)
            u[q] = *(const uint2*)(g_h + (size_t)p[q].x * DIM + c4);
#pragma unroll
        for (int q = 0; q < 4; q++) {
            const float v = __int_as_float(p[q].y);
            float2 f;
            f = __half22float2(*(const __half2*)&u[q].x);
            accA.x += v * f.x; accA.y += v * f.y;
            f = __half22float2(*(const __half2*)&u[q].y);
            accA.z += v * f.x; accA.w += v * f.y;
        }
#pragma unroll
        for (int q = 4; q < 8; q++) {
            const float v = __int_as_float(p[q].y);
            float2 f;
            f = __half22float2(*(const __half2*)&u[q].x);
            accB.x += v * f.x; accB.y += v * f.y;
            f = __half22float2(*(const __half2*)&u[q].y);
            accB.z += v * f.x; accB.w += v * f.y;
        }
    }
    for (; e + 4 <= end; e += 4) {
        int2 p[4];
#pragma unroll
        for (int q = 0; q < 4; q++) p[q] = g_epack[e + q];
        uint2 u[4];
#pragma unroll
        for (int q = 0; q < 4; q++)
            u[q] = *(const uint2*)(g_h + (size_t)p[q].x * DIM + c4);
#pragma unroll
        for (int q = 0; q < 4; q++) {
            const float v = __int_as_float(p[q].y);
            float2 f;
            f = __half22float2(*(const __half2*)&u[q].x);
            accA.x += v * f.x; accA.y += v * f.y;
            f = __half22float2(*(const __half2*)&u[q].y);
            accA.z += v * f.x; accA.w += v * f.y;
        }
    }
    for (; e < end; e++) {
        const int2 p = g_epack[e];
        const float v = __int_as_float(p.y);
        const uint2 u = *(const uint2*)(g_h + (size_t)p.x * DIM + c4);
        const float2 f01 = __half22float2(*(const __half2*)&u.x);
        const float2 f23 = __half22float2(*(const __half2*)&u.y);
        accA.x += v * f01.x;
        accA.y += v * f01.y;
        accA.z += v * f23.x;
        accA.w += v * f23.y;
    }

    const float4 o = make_float4(accA.x + accB.x, accA.y + accB.y,
                                 accA.z + accB.z, accA.w + accB.w);
    *(float4*)(out + (size_t)node * DIM + c4) = o;
}

// ---------------------------------------------------------------------------
// Launcher: 4 plain kernel launches (graph-capture safe).
// ---------------------------------------------------------------------------
extern "C" void kernel_launch(void* const* d_in, const int* in_sizes, int n_in,
                              void* d_out, int out_size) {
    const float* x    = (const float*)d_in[0];
    const float* W    = (const float*)d_in[1];
    const float* b    = (const float*)d_in[2];
    const float* vals = (const float*)d_in[3];
    const int*   rows = (const int*)d_in[4];
    const int*   cols = (const int*)d_in[5];
    float* out = (float*)d_out;

    (void)in_sizes; (void)n_in; (void)out_size;

    k_gemm_hist<<<GEMM_BLOCKS + HIST_BLOCKS, 256>>>(x, W, b, rows);
    k_scan<<<NCHUNKS, 256>>>();
    k_bucket<<<(N_EDGES + 255) / 256, 256>>>(rows, cols, vals);
    k_agg<<<(N_NODES + 7) / 8, 256>>>(out);
}